// round 16
// baseline (speedup 1.0000x reference)
#include <cuda_runtime.h>

#define NN 8192
#define HH 16
#define NHEAD 4

#define NCHUNK 256
#define CHUNK  (NN / NCHUNK)    // 32
#define WARMUP 64
#define SPANMAX (CHUNK + WARMUP)

#define DMAX 8
#define NF 495                  // #multi-indices |alpha|<=8 in dim 4 = C(12,4)
#define NPAIR 45                // #pairs a+b<=8 = C(10,2)
#define S_MAX 1.2f              // degree-8 truncation <= 1.2^9/9! ~ 1.4e-5

#define GAGG 32                 // agg blocks per head
#define KSUB 64                 // keys per sub-tile
#define NSUB 4                  // sub-tiles per block: 32*64*4 = 8192 keys
#define POWSTR 65               // padded key-stride for bank spread

// ---------------- device scratch (no allocations allowed) ----------------
__device__ float  g_Hseq[NN * HH];
__device__ float4 g_Q[NN * NHEAD];            // pre-scaled queries (x 0.5)
__device__ float4 g_K[NN * NHEAD];
__device__ float4 g_V[NN * NHEAD];

__device__ float  g_prepA[NCHUNK][24];        // 16 ksum, 4 maxk2, 4 maxq2
__device__ float  g_kbar[NHEAD][4];
__device__ int    g_flag;                     // 1 = Taylor path valid

__device__ float  g_Mpart[NHEAD * GAGG * NF * 5];   // writer-friendly layout
__device__ float4 g_M4[NHEAD][NF];
__device__ float  g_MD[NHEAD][NF];
__device__ float4 g_ctx[NN * NHEAD];          // attention context (normalized)

__device__ float  g_Pblk[64 * 3];

// last-block-done counters (zero-initialized; consumer resets after use)
__device__ int    g_cnt_lstm;
__device__ int    g_cnt_agg[NHEAD];
__device__ int    g_cnt_fin;

__device__ __forceinline__ float tanh_fast(float x) {
    float y;
    asm("tanh.approx.f32 %0, %1;" : "=f"(y) : "f"(x));
    return y;
}

// decode rank -> multi-index (a,b,c,d), enumeration order: a,b,c outer, d inner
__device__ __forceinline__ void unrank(int r, int& a, int& b, int& c, int& d) {
    a = 0;
    for (;;) { int m = DMAX - a; int cnt = (m + 1) * (m + 2) * (m + 3) / 6;
               if (r < cnt) break; r -= cnt; a++; }
    b = 0;
    for (;;) { int m = DMAX - a - b; int cnt = (m + 1) * (m + 2) / 2;
               if (r < cnt) break; r -= cnt; b++; }
    c = 0;
    for (;;) { int cnt = DMAX - a - b - c + 1;
               if (r < cnt) break; r -= cnt; c++; }
    d = r;
}

// pair rank for (a,b) with a+b<=DMAX, a outer, b inner
__device__ __forceinline__ int prank(int a, int b) {
    return a * (DMAX + 1) - (a * (a - 1)) / 2 + b;
}

__device__ __forceinline__ float inv_factorial4(int a, int b, int c, int d) {
    float fact[DMAX + 1];
    fact[0] = 1.0f;
#pragma unroll
    for (int n = 1; n <= DMAX; n++) fact[n] = fact[n - 1] * (float)n;
    return (1.0f / fact[a]) * (1.0f / fact[b]) * (1.0f / fact[c]) * (1.0f / fact[d]);
}

// ---------------- kernel 1: LSTM + QKV + stats + (last block) prepB --------
__global__ void __launch_bounds__(128, 1)
lstm_kernel(const float* __restrict__ t,
            const float* __restrict__ W_ih,
            const float* __restrict__ W_hh,
            const float* __restrict__ b_ih,
            const float* __restrict__ b_hh,
            const float* __restrict__ in_proj_w,
            const float* __restrict__ in_proj_b) {
    __shared__ float tsh[SPANMAX];
    __shared__ float Hloc[CHUNK][HH];
    __shared__ float qkvsh[CHUNK][49];   // raw acc (Q unscaled here), padded
    __shared__ int lastsh;

    const int blk    = blockIdx.x;
    const int wstart = blk * CHUNK;
    const int start  = max(0, wstart - WARMUP);
    const int nsteps = wstart + CHUNK - start;

    for (int i = threadIdx.x; i < nsteps; i += 128) tsh[i] = t[start + i];
    __syncthreads();

    if (threadIdx.x < 32) {
        const int lane = threadIdx.x;
        const bool lo = (lane < 16);
        const int r1 = lane, r2 = lane + 32;
        const float sc2 = lo ? 1.0f : 0.5f;

        float w1[HH], w2[HH];
#pragma unroll
        for (int k = 0; k < HH; k++) {
            w1[k] = W_hh[r1 * HH + k] * 0.5f;
            w2[k] = W_hh[r2 * HH + k] * sc2;
        }
        const float wi1 = W_ih[r1] * 0.5f, wi2 = W_ih[r2] * sc2;
        const float bb1 = (b_ih[r1] + b_hh[r1]) * 0.5f;
        const float bb2 = (b_ih[r2] + b_hh[r2]) * sc2;

        float h[HH];
#pragma unroll
        for (int k = 0; k < HH; k++) h[k] = 0.0f;
        float c = 0.0f;
        const int peer = (lane & 15) + 16;
        const int wloc = wstart - start;

#pragma unroll 4
        for (int sl = 0; sl < nsteps; sl++) {
            const float x = tsh[sl];
            float g1a = fmaf(wi1, x, bb1), g1b = 0.0f, g1c = 0.0f, g1d = 0.0f;
            float g2a = fmaf(wi2, x, bb2), g2b = 0.0f, g2c = 0.0f, g2d = 0.0f;
#pragma unroll
            for (int k = 0; k < HH; k += 4) {
                g1a = fmaf(w1[k],     h[k],     g1a);
                g1b = fmaf(w1[k + 1], h[k + 1], g1b);
                g1c = fmaf(w1[k + 2], h[k + 2], g1c);
                g1d = fmaf(w1[k + 3], h[k + 3], g1d);
                g2a = fmaf(w2[k],     h[k],     g2a);
                g2b = fmaf(w2[k + 1], h[k + 1], g2b);
                g2c = fmaf(w2[k + 2], h[k + 2], g2c);
                g2d = fmaf(w2[k + 3], h[k + 3], g2d);
            }
            const float g1 = (g1a + g1b) + (g1c + g1d);
            const float g2 = (g2a + g2b) + (g2c + g2d);

            const float a1 = fmaf(0.5f, tanh_fast(g1), 0.5f);
            const float th2 = tanh_fast(g2);
            const float a2 = lo ? th2 : fmaf(0.5f, th2, 0.5f);

            const float fg = __shfl_sync(0xffffffffu, a1, peer);
            const float og = __shfl_sync(0xffffffffu, a2, peer);

            c = fmaf(fg, c, a1 * a2);
            const float hn = og * tanh_fast(c);

            if (lane < 16 && sl >= wloc) {
                Hloc[sl - wloc][lane] = hn;
                g_Hseq[(start + sl) * HH + lane] = hn;
            }

#pragma unroll
            for (int k = 0; k < HH; k++)
                h[k] = __shfl_sync(0xffffffffu, hn, k);
        }
    }
    __syncthreads();

    // fused QKV: 32 rows x 48 outputs
    for (int e = threadIdx.x; e < CHUNK * 48; e += 128) {
        const int nl = e / 48;
        const int j  = e % 48;
        const int n  = wstart + nl;
        float acc = __ldg(in_proj_b + j);
#pragma unroll
        for (int k = 0; k < HH; k++)
            acc = fmaf(__ldg(in_proj_w + j * HH + k), Hloc[nl][k], acc);

        qkvsh[nl][j] = acc;
        if (j < 16)       ((float*)g_Q)[n * HH + j]        = acc * 0.5f;  // 1/sqrt(HD)
        else if (j < 32)  ((float*)g_K)[n * HH + (j - 16)] = acc;
        else              ((float*)g_V)[n * HH + (j - 32)] = acc;
    }
    __syncthreads();

    // fused per-chunk stats
    const int tid = threadIdx.x;
    if (tid < 16) {
        float s = 0.0f;
#pragma unroll
        for (int r = 0; r < CHUNK; r++) s += qkvsh[r][16 + tid];
        g_prepA[blk][tid] = s;
    } else if (tid < 20) {
        const int h = tid - 16;
        float m = 0.0f;
#pragma unroll
        for (int r = 0; r < CHUNK; r++) {
            const float k0 = qkvsh[r][16 + h * 4 + 0];
            const float k1 = qkvsh[r][16 + h * 4 + 1];
            const float k2 = qkvsh[r][16 + h * 4 + 2];
            const float k3 = qkvsh[r][16 + h * 4 + 3];
            m = fmaxf(m, k0 * k0 + k1 * k1 + k2 * k2 + k3 * k3);
        }
        g_prepA[blk][tid] = m;
    } else if (tid < 24) {
        const int h = tid - 20;
        float m = 0.0f;
#pragma unroll
        for (int r = 0; r < CHUNK; r++) {
            const float q0 = 0.5f * qkvsh[r][h * 4 + 0];
            const float q1 = 0.5f * qkvsh[r][h * 4 + 1];
            const float q2 = 0.5f * qkvsh[r][h * 4 + 2];
            const float q3 = 0.5f * qkvsh[r][h * 4 + 3];
            m = fmaxf(m, q0 * q0 + q1 * q1 + q2 * q2 + q3 * q3);
        }
        g_prepA[blk][tid] = m;
    }

    // last-block-done: final block computes kbar + bound flag (old prepB)
    __threadfence();
    __syncthreads();
    if (tid == 0) {
        const int r = atomicAdd(&g_cnt_lstm, 1);
        lastsh = (r == NCHUNK - 1) ? 1 : 0;
        if (lastsh) g_cnt_lstm = 0;          // reset for next graph replay
    }
    __syncthreads();
    if (lastsh) {
        __threadfence();
        __shared__ float s[24];
        if (tid < 24) {
            float r = g_prepA[0][tid];
            if (tid < 16) { for (int b = 1; b < NCHUNK; b++) r += g_prepA[b][tid]; }
            else          { for (int b = 1; b < NCHUNK; b++) r = fmaxf(r, g_prepA[b][tid]); }
            s[tid] = r;
        }
        __syncthreads();
        if (tid == 0) {
            float kbar[16];
#pragma unroll
            for (int i = 0; i < 16; i++) {
                kbar[i] = s[i] * (1.0f / (float)NN);
                ((float*)g_kbar)[i] = kbar[i];
            }
            float bound = 0.0f;
#pragma unroll
            for (int h = 0; h < NHEAD; h++) {
                const float kb = sqrtf(kbar[h*4]*kbar[h*4] + kbar[h*4+1]*kbar[h*4+1]
                                     + kbar[h*4+2]*kbar[h*4+2] + kbar[h*4+3]*kbar[h*4+3]);
                const float bk = sqrtf(s[16 + h]) + kb;
                const float bq = sqrtf(s[20 + h]);
                bound = fmaxf(bound, bq * bk);
            }
            g_flag = (bound <= S_MAX) ? 1 : 0;
        }
    }
}

// ---------------- kernel 2: Taylor aggregation + (last block/head) combine -
__global__ void __launch_bounds__(512, 2) agg_kernel() {
    if (g_flag == 0) return;

    __shared__ float  pow1[4 * (DMAX + 1) * POWSTR];
    __shared__ float  pXY[NPAIR * POWSTR];
    __shared__ float  pZW[NPAIR * POWSTR];
    __shared__ float4 Vt[KSUB];
    __shared__ int lastsh;

    const int tid   = threadIdx.x;
    const int chunk = blockIdx.x;
    const int h     = blockIdx.y;

    int ai = 0, bi = 0, ci = 0, di = 0;
    if (tid < NF) unrank(tid, ai, bi, ci, di);
    const float* xy = &pXY[prank(ai, bi) * POWSTR];
    const float* zw = &pZW[prank(ci, di) * POWSTR];

    float u0 = 0, u1 = 0, u2 = 0, u3 = 0, ud = 0;

    for (int sub = 0; sub < NSUB; sub++) {
        const int kb0 = chunk * (KSUB * NSUB) + sub * KSUB;

        if (tid < 256) {
            const int var = tid >> 6, key = tid & 63;
            const float kv = ((const float*)&g_K[(kb0 + key) * NHEAD + h])[var];
            float x = kv - g_kbar[h][var];
            float p = 1.0f;
#pragma unroll
            for (int deg = 0; deg <= DMAX; deg++) {
                pow1[(var * (DMAX + 1) + deg) * POWSTR + key] = p;
                p *= x;
            }
        } else if (tid < 320) {
            const int key = tid - 256;
            Vt[key] = g_V[(kb0 + key) * NHEAD + h];
        }
        __syncthreads();

        for (int idx = tid; idx < NPAIR * KSUB; idx += 512) {
            const int r = idx >> 6, key = idx & 63;
            int a = 0, rr = r;
            while (rr >= (DMAX + 1 - a)) { rr -= (DMAX + 1 - a); a++; }
            const int b = rr;
            pXY[r * POWSTR + key] = pow1[(0 * (DMAX + 1) + a) * POWSTR + key]
                                  * pow1[(1 * (DMAX + 1) + b) * POWSTR + key];
            pZW[r * POWSTR + key] = pow1[(2 * (DMAX + 1) + a) * POWSTR + key]
                                  * pow1[(3 * (DMAX + 1) + b) * POWSTR + key];
        }
        __syncthreads();

        if (tid < NF) {
#pragma unroll 4
            for (int key = 0; key < KSUB; key++) {
                const float4 v = Vt[key];
                const float m = xy[key] * zw[key];
                u0 = fmaf(m, v.x, u0); u1 = fmaf(m, v.y, u1);
                u2 = fmaf(m, v.z, u2); u3 = fmaf(m, v.w, u3);
                ud += m;
            }
        }
        __syncthreads();
    }

    if (tid < NF) {
        float* p = &g_Mpart[(((h * GAGG) + chunk) * NF + tid) * 5];
        p[0] = u0; p[1] = u1; p[2] = u2; p[3] = u3; p[4] = ud;
    }

    // last block of this head performs the combine (old combine_kernel)
    __threadfence();
    __syncthreads();
    if (tid == 0) {
        const int r = atomicAdd(&g_cnt_agg[h], 1);
        lastsh = (r == GAGG - 1) ? 1 : 0;
        if (lastsh) g_cnt_agg[h] = 0;        // reset for next graph replay
    }
    __syncthreads();
    if (lastsh) {
        __threadfence();
        for (int idx = tid; idx < NF * 5; idx += 512) {
            const int j    = idx % 5;
            const int feat = idx / 5;
            float sum = 0.0f;
#pragma unroll 8
            for (int ch = 0; ch < GAGG; ch++)
                sum += g_Mpart[(((h * GAGG) + ch) * NF + feat) * 5 + j];

            int fa, fb, fc, fd;
            unrank(feat, fa, fb, fc, fd);
            sum *= inv_factorial4(fa, fb, fc, fd);

            if (j < 4) ((float*)&g_M4[h][feat])[j] = sum;
            else       g_MD[h][feat] = sum;
        }
    }
}

// ---------------- kernel 3: query pass (Taylor, or exact fallback) ---------
__global__ void tquery_kernel() {
    const int tid = threadIdx.x;
    const int h = blockIdx.y;
    const int q = blockIdx.x * 256 + tid;
    const float4 qv = g_Q[q * NHEAD + h];

    if (g_flag != 0) {
        __shared__ float4 Msh4[NF];
        __shared__ float  MshD[NF];
        for (int i = tid; i < NF; i += 256) {
            Msh4[i] = g_M4[h][i];
            MshD[i] = g_MD[h][i];
        }
        __syncthreads();

        float a0 = 0, a1 = 0, a2 = 0, a3 = 0, dn = 0;
        int idx = 0;
        float pa = 1.0f;
        for (int a = 0; a <= DMAX; a++) {
            float pab = pa;
            for (int b = 0; b <= DMAX - a; b++) {
                float pabc = pab;
                for (int c = 0; c <= DMAX - a - b; c++) {
                    float m = pabc;
                    for (int d = 0; d <= DMAX - a - b - c; d++) {
                        const float4 M4 = Msh4[idx];
                        const float  MD = MshD[idx];
                        a0 = fmaf(m, M4.x, a0);
                        a1 = fmaf(m, M4.y, a1);
                        a2 = fmaf(m, M4.z, a2);
                        a3 = fmaf(m, M4.w, a3);
                        dn = fmaf(m, MD, dn);
                        idx++;
                        m *= qv.w;
                    }
                    pabc *= qv.z;
                }
                pab *= qv.y;
            }
            pa *= qv.x;
        }
        const float inv = __fdividef(1.0f, dn);
        g_ctx[q * NHEAD + h] = make_float4(a0 * inv, a1 * inv, a2 * inv, a3 * inv);
    } else {
        // exact fallback (dead in practice; correctness guarantee)
        float den = 0.0f;
        float4 acc = make_float4(0.0f, 0.0f, 0.0f, 0.0f);
        for (int k = 0; k < NN; k++) {
            const float4 kv = g_K[k * NHEAD + h];
            float sc = qv.x * kv.x;
            sc = fmaf(qv.y, kv.y, sc);
            sc = fmaf(qv.z, kv.z, sc);
            sc = fmaf(qv.w, kv.w, sc);
            const float p = __expf(sc);
            den += p;
            const float4 vv = g_V[k * NHEAD + h];
            acc.x = fmaf(p, vv.x, acc.x);
            acc.y = fmaf(p, vv.y, acc.y);
            acc.z = fmaf(p, vv.z, acc.z);
            acc.w = fmaf(p, vv.w, acc.w);
        }
        const float inv = __fdividef(1.0f, den);
        g_ctx[q * NHEAD + h] = make_float4(acc.x * inv, acc.y * inv,
                                           acc.z * inv, acc.w * inv);
    }
}

// ---------------- kernel 4: finalize + (last block) reduce ------------------
__global__ void finalize_kernel(const float* __restrict__ out_proj_w,
                                const float* __restrict__ out_proj_b,
                                const float* __restrict__ ln_w,
                                const float* __restrict__ ln_b,
                                const float* __restrict__ out_w,
                                const float* __restrict__ out_b,
                                float* __restrict__ out) {
    __shared__ int lastsh;
    const int q = blockIdx.x * 128 + threadIdx.x;

    float ctx[HH];
#pragma unroll
    for (int h = 0; h < NHEAD; h++) {
        const float4 cv = g_ctx[q * NHEAD + h];
        ctx[h * 4 + 0] = cv.x; ctx[h * 4 + 1] = cv.y;
        ctx[h * 4 + 2] = cv.z; ctx[h * 4 + 3] = cv.w;
    }

    float y[HH];
#pragma unroll
    for (int r = 0; r < HH; r++) {
        float t = out_proj_b[r];
#pragma unroll
        for (int cc = 0; cc < HH; cc++)
            t = fmaf(__ldg(out_proj_w + r * HH + cc), ctx[cc], t);
        y[r] = t + g_Hseq[q * HH + r];
    }

    float mu = 0.0f;
#pragma unroll
    for (int r = 0; r < HH; r++) mu += y[r];
    mu *= (1.0f / HH);
    float var = 0.0f;
#pragma unroll
    for (int r = 0; r < HH; r++) {
        const float d = y[r] - mu;
        var = fmaf(d, d, var);
    }
    var *= (1.0f / HH);
    const float rstd = rsqrtf(var + 1e-5f);

    float z[HH];
#pragma unroll
    for (int r = 0; r < HH; r++)
        z[r] = (y[r] - mu) * rstd * ln_w[r] + ln_b[r];

    float raw[3];
#pragma unroll
    for (int j = 0; j < 3; j++) {
        float t = 0.0f;
#pragma unroll
        for (int r = 0; r < HH; r++)
            t = fmaf(__ldg(out_w + j * HH + r), z[r], t);
        raw[j] = t;
    }

    __shared__ float wsum[4][3];
    const int lane = threadIdx.x & 31;
    const int wid  = threadIdx.x >> 5;
#pragma unroll
    for (int j = 0; j < 3; j++) {
        float v = raw[j];
#pragma unroll
        for (int off = 16; off > 0; off >>= 1)
            v += __shfl_xor_sync(0xffffffffu, v, off);
        if (lane == 0) wsum[wid][j] = v;
    }
    __syncthreads();
    if (threadIdx.x < 3) {
        float v = 0.0f;
#pragma unroll
        for (int w = 0; w < 4; w++) v += wsum[w][threadIdx.x];
        g_Pblk[blockIdx.x * 3 + threadIdx.x] = v;
    }

    // last-block-done: final reduction to the 3 outputs
    __threadfence();
    __syncthreads();
    if (threadIdx.x == 0) {
        const int r = atomicAdd(&g_cnt_fin, 1);
        lastsh = (r == (int)gridDim.x - 1) ? 1 : 0;
        if (lastsh) g_cnt_fin = 0;           // reset for next graph replay
    }
    __syncthreads();
    if (lastsh) {
        __threadfence();
        if (threadIdx.x < 3) {
            float s = 0.0f;
            for (int b = 0; b < 64; b++) s += g_Pblk[b * 3 + threadIdx.x];
            out[threadIdx.x] = s * (1.0f / (float)NN) + out_b[threadIdx.x];
        }
    }
}

// ---------------- launch ----------------
extern "C" void kernel_launch(void* const* d_in, const int* in_sizes, int n_in,
                              void* d_out, int out_size) {
    (void)in_sizes; (void)n_in; (void)out_size;
    const float* t          = (const float*)d_in[0];
    const float* W_ih       = (const float*)d_in[1];
    const float* W_hh       = (const float*)d_in[2];
    const float* b_ih       = (const float*)d_in[3];
    const float* b_hh       = (const float*)d_in[4];
    const float* in_proj_w  = (const float*)d_in[5];
    const float* in_proj_b  = (const float*)d_in[6];
    const float* out_proj_w = (const float*)d_in[7];
    const float* out_proj_b = (const float*)d_in[8];
    const float* ln_w       = (const float*)d_in[9];
    const float* ln_b       = (const float*)d_in[10];
    const float* out_w      = (const float*)d_in[11];
    const float* out_b      = (const float*)d_in[12];
    float* out = (float*)d_out;

    lstm_kernel<<<NCHUNK, 128>>>(t, W_ih, W_hh, b_ih, b_hh, in_proj_w, in_proj_b);
    dim3 agrid(GAGG, NHEAD);
    agg_kernel<<<agrid, 512>>>();
    dim3 tgrid(NN / 256, NHEAD);
    tquery_kernel<<<tgrid, 256>>>();
    finalize_kernel<<<NN / 128, 128>>>(out_proj_w, out_proj_b, ln_w, ln_b,
                                       out_w, out_b, out);
}

// round 17
// speedup vs baseline: 1.0850x; 1.0850x over previous
#include <cuda_runtime.h>

#define NN 8192
#define HH 16
#define NHEAD 4

#define NCHUNK 256
#define CHUNK  (NN / NCHUNK)    // 32
#define WARMUP 64
#define SPANMAX (CHUNK + WARMUP)

#define DMAX 8
#define NF 495                  // #multi-indices |alpha|<=8 in dim 4 = C(12,4)
#define NPAIR 45                // #pairs a+b<=8 = C(10,2)
#define S_MAX 1.2f              // degree-8 truncation <= 1.2^9/9! ~ 1.4e-5

#define GAGG 32                 // agg blocks per head
#define KSUB 64                 // keys per sub-tile
#define NSUB 4                  // 32*64*4 = 8192 keys
#define POWSTR 65               // padded key-stride for bank spread

#define GFIN 128                // tqfin blocks (64 q each)

// ---------------- device scratch (no allocations allowed) ----------------
__device__ float  g_Hseq[NN * HH];
__device__ float4 g_Q[NN * NHEAD];            // pre-scaled queries (x 0.5)
__device__ float4 g_K[NN * NHEAD];
__device__ float4 g_V[NN * NHEAD];

__device__ float  g_prepA[NCHUNK][24];        // 16 ksum, 4 maxk2, 4 maxq2
__device__ float  g_kbar[NHEAD][4];
__device__ int    g_flag;                     // 1 = Taylor path valid

__device__ float  g_Mpart[NHEAD * GAGG * NF * 5];
__device__ float4 g_M4[NHEAD][NF];
__device__ float  g_MD[NHEAD][NF];

__device__ float  g_Pblk[GFIN * 3];

// last-block-done counters (zero-initialized; consumer resets after use)
__device__ int    g_cnt_lstm;
__device__ int    g_cnt_agg[NHEAD];
__device__ int    g_cnt_fin;

__device__ __forceinline__ float tanh_fast(float x) {
    float y;
    asm("tanh.approx.f32 %0, %1;" : "=f"(y) : "f"(x));
    return y;
}

// decode rank -> multi-index (a,b,c,d), enumeration order: a,b,c outer, d inner
__device__ __forceinline__ void unrank(int r, int& a, int& b, int& c, int& d) {
    a = 0;
    for (;;) { int m = DMAX - a; int cnt = (m + 1) * (m + 2) * (m + 3) / 6;
               if (r < cnt) break; r -= cnt; a++; }
    b = 0;
    for (;;) { int m = DMAX - a - b; int cnt = (m + 1) * (m + 2) / 2;
               if (r < cnt) break; r -= cnt; b++; }
    c = 0;
    for (;;) { int cnt = DMAX - a - b - c + 1;
               if (r < cnt) break; r -= cnt; c++; }
    d = r;
}

// pair rank for (a,b) with a+b<=DMAX, a outer, b inner
__device__ __forceinline__ int prank(int a, int b) {
    return a * (DMAX + 1) - (a * (a - 1)) / 2 + b;
}

__device__ __forceinline__ float inv_factorial4(int a, int b, int c, int d) {
    float fact[DMAX + 1];
    fact[0] = 1.0f;
#pragma unroll
    for (int n = 1; n <= DMAX; n++) fact[n] = fact[n - 1] * (float)n;
    return (1.0f / fact[a]) * (1.0f / fact[b]) * (1.0f / fact[c]) * (1.0f / fact[d]);
}

// ---------------- kernel 1: LSTM + QKV + stats + (last block) prepB --------
__global__ void __launch_bounds__(128, 1)
lstm_kernel(const float* __restrict__ t,
            const float* __restrict__ W_ih,
            const float* __restrict__ W_hh,
            const float* __restrict__ b_ih,
            const float* __restrict__ b_hh,
            const float* __restrict__ in_proj_w,
            const float* __restrict__ in_proj_b) {
    __shared__ float tsh[SPANMAX];
    __shared__ float Hloc[CHUNK][HH];
    __shared__ float qkvsh[CHUNK][49];
    __shared__ int lastsh;

    const int blk    = blockIdx.x;
    const int wstart = blk * CHUNK;
    const int start  = max(0, wstart - WARMUP);
    const int nsteps = wstart + CHUNK - start;

    for (int i = threadIdx.x; i < nsteps; i += 128) tsh[i] = t[start + i];
    __syncthreads();

    if (threadIdx.x < 32) {
        const int lane = threadIdx.x;
        const bool lo = (lane < 16);
        const int r1 = lane, r2 = lane + 32;
        const float sc2 = lo ? 1.0f : 0.5f;

        float w1[HH], w2[HH];
#pragma unroll
        for (int k = 0; k < HH; k++) {
            w1[k] = W_hh[r1 * HH + k] * 0.5f;
            w2[k] = W_hh[r2 * HH + k] * sc2;
        }
        const float wi1 = W_ih[r1] * 0.5f, wi2 = W_ih[r2] * sc2;
        const float bb1 = (b_ih[r1] + b_hh[r1]) * 0.5f;
        const float bb2 = (b_ih[r2] + b_hh[r2]) * sc2;

        float h[HH];
#pragma unroll
        for (int k = 0; k < HH; k++) h[k] = 0.0f;
        float c = 0.0f;
        const int peer = (lane & 15) + 16;
        const int wloc = wstart - start;

#pragma unroll 4
        for (int sl = 0; sl < nsteps; sl++) {
            const float x = tsh[sl];
            float g1a = fmaf(wi1, x, bb1), g1b = 0.0f, g1c = 0.0f, g1d = 0.0f;
            float g2a = fmaf(wi2, x, bb2), g2b = 0.0f, g2c = 0.0f, g2d = 0.0f;
#pragma unroll
            for (int k = 0; k < HH; k += 4) {
                g1a = fmaf(w1[k],     h[k],     g1a);
                g1b = fmaf(w1[k + 1], h[k + 1], g1b);
                g1c = fmaf(w1[k + 2], h[k + 2], g1c);
                g1d = fmaf(w1[k + 3], h[k + 3], g1d);
                g2a = fmaf(w2[k],     h[k],     g2a);
                g2b = fmaf(w2[k + 1], h[k + 1], g2b);
                g2c = fmaf(w2[k + 2], h[k + 2], g2c);
                g2d = fmaf(w2[k + 3], h[k + 3], g2d);
            }
            const float g1 = (g1a + g1b) + (g1c + g1d);
            const float g2 = (g2a + g2b) + (g2c + g2d);

            const float a1 = fmaf(0.5f, tanh_fast(g1), 0.5f);
            const float th2 = tanh_fast(g2);
            const float a2 = lo ? th2 : fmaf(0.5f, th2, 0.5f);

            const float fg = __shfl_sync(0xffffffffu, a1, peer);
            const float og = __shfl_sync(0xffffffffu, a2, peer);

            c = fmaf(fg, c, a1 * a2);
            const float hn = og * tanh_fast(c);

            if (lane < 16 && sl >= wloc) {
                Hloc[sl - wloc][lane] = hn;
                g_Hseq[(start + sl) * HH + lane] = hn;
            }

#pragma unroll
            for (int k = 0; k < HH; k++)
                h[k] = __shfl_sync(0xffffffffu, hn, k);
        }
    }
    __syncthreads();

    // fused QKV: 32 rows x 48 outputs
    for (int e = threadIdx.x; e < CHUNK * 48; e += 128) {
        const int nl = e / 48;
        const int j  = e % 48;
        const int n  = wstart + nl;
        float acc = __ldg(in_proj_b + j);
#pragma unroll
        for (int k = 0; k < HH; k++)
            acc = fmaf(__ldg(in_proj_w + j * HH + k), Hloc[nl][k], acc);

        qkvsh[nl][j] = acc;
        if (j < 16)       ((float*)g_Q)[n * HH + j]        = acc * 0.5f;  // 1/sqrt(HD)
        else if (j < 32)  ((float*)g_K)[n * HH + (j - 16)] = acc;
        else              ((float*)g_V)[n * HH + (j - 32)] = acc;
    }
    __syncthreads();

    // fused per-chunk stats
    const int tid = threadIdx.x;
    if (tid < 16) {
        float s = 0.0f;
#pragma unroll
        for (int r = 0; r < CHUNK; r++) s += qkvsh[r][16 + tid];
        g_prepA[blk][tid] = s;
    } else if (tid < 20) {
        const int h = tid - 16;
        float m = 0.0f;
#pragma unroll
        for (int r = 0; r < CHUNK; r++) {
            const float k0 = qkvsh[r][16 + h * 4 + 0];
            const float k1 = qkvsh[r][16 + h * 4 + 1];
            const float k2 = qkvsh[r][16 + h * 4 + 2];
            const float k3 = qkvsh[r][16 + h * 4 + 3];
            m = fmaxf(m, k0 * k0 + k1 * k1 + k2 * k2 + k3 * k3);
        }
        g_prepA[blk][tid] = m;
    } else if (tid < 24) {
        const int h = tid - 20;
        float m = 0.0f;
#pragma unroll
        for (int r = 0; r < CHUNK; r++) {
            const float q0 = 0.5f * qkvsh[r][h * 4 + 0];
            const float q1 = 0.5f * qkvsh[r][h * 4 + 1];
            const float q2 = 0.5f * qkvsh[r][h * 4 + 2];
            const float q3 = 0.5f * qkvsh[r][h * 4 + 3];
            m = fmaxf(m, q0 * q0 + q1 * q1 + q2 * q2 + q3 * q3);
        }
        g_prepA[blk][tid] = m;
    }

    // last-block-done: final block computes kbar + bound flag
    __threadfence();
    __syncthreads();
    if (tid == 0) {
        const int r = atomicAdd(&g_cnt_lstm, 1);
        lastsh = (r == NCHUNK - 1) ? 1 : 0;
        if (lastsh) g_cnt_lstm = 0;
    }
    __syncthreads();
    if (lastsh) {
        __threadfence();
        __shared__ float s[24];
        if (tid < 24) {
            float r = g_prepA[0][tid];
            if (tid < 16) { for (int b = 1; b < NCHUNK; b++) r += g_prepA[b][tid]; }
            else          { for (int b = 1; b < NCHUNK; b++) r = fmaxf(r, g_prepA[b][tid]); }
            s[tid] = r;
        }
        __syncthreads();
        if (tid == 0) {
            float kbar[16];
#pragma unroll
            for (int i = 0; i < 16; i++) {
                kbar[i] = s[i] * (1.0f / (float)NN);
                ((float*)g_kbar)[i] = kbar[i];
            }
            float bound = 0.0f;
#pragma unroll
            for (int h = 0; h < NHEAD; h++) {
                const float kb = sqrtf(kbar[h*4]*kbar[h*4] + kbar[h*4+1]*kbar[h*4+1]
                                     + kbar[h*4+2]*kbar[h*4+2] + kbar[h*4+3]*kbar[h*4+3]);
                const float bk = sqrtf(s[16 + h]) + kb;
                const float bq = sqrtf(s[20 + h]);
                bound = fmaxf(bound, bq * bk);
            }
            g_flag = (bound <= S_MAX) ? 1 : 0;
        }
    }
}

// ---------------- kernel 2: Taylor aggregation + (last block/head) combine -
__global__ void __launch_bounds__(512, 2) agg_kernel() {
    if (g_flag == 0) return;

    __shared__ float  pow1[4 * (DMAX + 1) * POWSTR];
    __shared__ float  pXY[NPAIR * POWSTR];
    __shared__ float  pZW[NPAIR * POWSTR];
    __shared__ float4 Vt[KSUB];
    __shared__ int lastsh;

    const int tid   = threadIdx.x;
    const int chunk = blockIdx.x;
    const int h     = blockIdx.y;

    int ai = 0, bi = 0, ci = 0, di = 0;
    if (tid < NF) unrank(tid, ai, bi, ci, di);
    const float* xy = &pXY[prank(ai, bi) * POWSTR];
    const float* zw = &pZW[prank(ci, di) * POWSTR];

    float u0 = 0, u1 = 0, u2 = 0, u3 = 0, ud = 0;

    for (int sub = 0; sub < NSUB; sub++) {
        const int kb0 = chunk * (KSUB * NSUB) + sub * KSUB;

        if (tid < 256) {
            const int var = tid >> 6, key = tid & 63;
            const float kv = ((const float*)&g_K[(kb0 + key) * NHEAD + h])[var];
            float x = kv - g_kbar[h][var];
            float p = 1.0f;
#pragma unroll
            for (int deg = 0; deg <= DMAX; deg++) {
                pow1[(var * (DMAX + 1) + deg) * POWSTR + key] = p;
                p *= x;
            }
        } else if (tid < 320) {
            const int key = tid - 256;
            Vt[key] = g_V[(kb0 + key) * NHEAD + h];
        }
        __syncthreads();

        for (int idx = tid; idx < NPAIR * KSUB; idx += 512) {
            const int r = idx >> 6, key = idx & 63;
            int a = 0, rr = r;
            while (rr >= (DMAX + 1 - a)) { rr -= (DMAX + 1 - a); a++; }
            const int b = rr;
            pXY[r * POWSTR + key] = pow1[(0 * (DMAX + 1) + a) * POWSTR + key]
                                  * pow1[(1 * (DMAX + 1) + b) * POWSTR + key];
            pZW[r * POWSTR + key] = pow1[(2 * (DMAX + 1) + a) * POWSTR + key]
                                  * pow1[(3 * (DMAX + 1) + b) * POWSTR + key];
        }
        __syncthreads();

        if (tid < NF) {
#pragma unroll 4
            for (int key = 0; key < KSUB; key++) {
                const float4 v = Vt[key];
                const float m = xy[key] * zw[key];
                u0 = fmaf(m, v.x, u0); u1 = fmaf(m, v.y, u1);
                u2 = fmaf(m, v.z, u2); u3 = fmaf(m, v.w, u3);
                ud += m;
            }
        }
        __syncthreads();
    }

    if (tid < NF) {
        float* p = &g_Mpart[(((h * GAGG) + chunk) * NF + tid) * 5];
        p[0] = u0; p[1] = u1; p[2] = u2; p[3] = u3; p[4] = ud;
    }

    // last block of this head performs the combine
    __threadfence();
    __syncthreads();
    if (tid == 0) {
        const int r = atomicAdd(&g_cnt_agg[h], 1);
        lastsh = (r == GAGG - 1) ? 1 : 0;
        if (lastsh) g_cnt_agg[h] = 0;
    }
    __syncthreads();
    if (lastsh) {
        __threadfence();
        for (int idx = tid; idx < NF * 5; idx += 512) {
            const int j    = idx % 5;
            const int feat = idx / 5;
            float sum = 0.0f;
#pragma unroll 8
            for (int ch = 0; ch < GAGG; ch++)
                sum += g_Mpart[(((h * GAGG) + ch) * NF + feat) * 5 + j];

            int fa, fb, fc, fd;
            unrank(feat, fa, fb, fc, fd);
            sum *= inv_factorial4(fa, fb, fc, fd);

            if (j < 4) ((float*)&g_M4[h][feat])[j] = sum;
            else       g_MD[h][feat] = sum;
        }
    }
}

// ---------------- kernel 3: fused query pass + finalize + reduce ------------
// 128 blocks x 256 threads. Warp w: head = w & 3, qgroup = w >> 2;
// lane handles q = blk*64 + qgroup*32 + lane (table reads warp-uniform).
// ctx staged in smem; threads 0..63 run out_proj+LN+readout; last block
// emits the 3 outputs.
__global__ void __launch_bounds__(256, 1)
tqfin_kernel(const float* __restrict__ out_proj_w,
             const float* __restrict__ out_proj_b,
             const float* __restrict__ ln_w,
             const float* __restrict__ ln_b,
             const float* __restrict__ out_w,
             const float* __restrict__ out_b,
             float* __restrict__ out) {
    __shared__ float4 Msh4[NHEAD * NF];
    __shared__ float  MshD[NHEAD * NF];
    __shared__ float  ctxsh[64][HH + 1];
    __shared__ float  wsum[2][3];
    __shared__ int lastsh;

    const int tid  = threadIdx.x;
    const int blk  = blockIdx.x;
    const int lane = tid & 31;
    const int w    = tid >> 5;
    const int head = w & 3;
    const int qloc = (w >> 2) * 32 + lane;   // 0..63
    const int q    = blk * 64 + qloc;
    const int flag = g_flag;

    if (flag) {
        for (int i = tid; i < NHEAD * NF; i += 256) {
            Msh4[i] = ((const float4*)g_M4)[i];
            MshD[i] = ((const float*)g_MD)[i];
        }
    }
    __syncthreads();

    const float4 qv = g_Q[q * NHEAD + head];
    float a0 = 0, a1 = 0, a2 = 0, a3 = 0, dn = 0;

    if (flag) {
        const float4* M4 = &Msh4[head * NF];
        const float*  MD = &MshD[head * NF];
        int idx = 0;
        float pa = 1.0f;
        for (int a = 0; a <= DMAX; a++) {
            float pab = pa;
            for (int b = 0; b <= DMAX - a; b++) {
                float pabc = pab;
                for (int c = 0; c <= DMAX - a - b; c++) {
                    float m = pabc;
                    for (int d = 0; d <= DMAX - a - b - c; d++) {
                        const float4 M = M4[idx];
                        const float  D = MD[idx];
                        a0 = fmaf(m, M.x, a0);
                        a1 = fmaf(m, M.y, a1);
                        a2 = fmaf(m, M.z, a2);
                        a3 = fmaf(m, M.w, a3);
                        dn = fmaf(m, D, dn);
                        idx++;
                        m *= qv.w;
                    }
                    pabc *= qv.z;
                }
                pab *= qv.y;
            }
            pa *= qv.x;
        }
    } else {
        // exact fallback (dead in practice; correctness guarantee)
        for (int k = 0; k < NN; k++) {
            const float4 kv = g_K[k * NHEAD + head];
            float sc = qv.x * kv.x;
            sc = fmaf(qv.y, kv.y, sc);
            sc = fmaf(qv.z, kv.z, sc);
            sc = fmaf(qv.w, kv.w, sc);
            const float p = __expf(sc);
            dn += p;
            const float4 vv = g_V[k * NHEAD + head];
            a0 = fmaf(p, vv.x, a0);
            a1 = fmaf(p, vv.y, a1);
            a2 = fmaf(p, vv.z, a2);
            a3 = fmaf(p, vv.w, a3);
        }
    }

    const float inv = __fdividef(1.0f, dn);
    ctxsh[qloc][head * 4 + 0] = a0 * inv;
    ctxsh[qloc][head * 4 + 1] = a1 * inv;
    ctxsh[qloc][head * 4 + 2] = a2 * inv;
    ctxsh[qloc][head * 4 + 3] = a3 * inv;
    __syncthreads();

    // finalize: threads 0..63, one query each
    if (tid < 64) {
        const int qq = blk * 64 + tid;

        float y[HH];
#pragma unroll
        for (int r = 0; r < HH; r++) {
            float tacc = out_proj_b[r];
#pragma unroll
            for (int cc = 0; cc < HH; cc++)
                tacc = fmaf(__ldg(out_proj_w + r * HH + cc), ctxsh[tid][cc], tacc);
            y[r] = tacc + g_Hseq[qq * HH + r];
        }

        float mu = 0.0f;
#pragma unroll
        for (int r = 0; r < HH; r++) mu += y[r];
        mu *= (1.0f / HH);
        float var = 0.0f;
#pragma unroll
        for (int r = 0; r < HH; r++) {
            const float d = y[r] - mu;
            var = fmaf(d, d, var);
        }
        var *= (1.0f / HH);
        const float rstd = rsqrtf(var + 1e-5f);

        float z[HH];
#pragma unroll
        for (int r = 0; r < HH; r++)
            z[r] = (y[r] - mu) * rstd * ln_w[r] + ln_b[r];

        float raw[3];
#pragma unroll
        for (int j = 0; j < 3; j++) {
            float tacc = 0.0f;
#pragma unroll
            for (int r = 0; r < HH; r++)
                tacc = fmaf(__ldg(out_w + j * HH + r), z[r], tacc);
            raw[j] = tacc;
        }

#pragma unroll
        for (int j = 0; j < 3; j++) {
            float v = raw[j];
#pragma unroll
            for (int off = 16; off > 0; off >>= 1)
                v += __shfl_xor_sync(0xffffffffu, v, off);
            if (lane == 0) wsum[w][j] = v;
        }
    }
    __syncthreads();
    if (tid < 3)
        g_Pblk[blk * 3 + tid] = wsum[0][tid] + wsum[1][tid];

    // last-block-done: final reduction to the 3 outputs
    __threadfence();
    __syncthreads();
    if (tid == 0) {
        const int r = atomicAdd(&g_cnt_fin, 1);
        lastsh = (r == GFIN - 1) ? 1 : 0;
        if (lastsh) g_cnt_fin = 0;
    }
    __syncthreads();
    if (lastsh) {
        __threadfence();
        if (tid < 3) {
            float s = 0.0f;
            for (int b = 0; b < GFIN; b++) s += g_Pblk[b * 3 + tid];
            out[tid] = s * (1.0f / (float)NN) + out_b[tid];
        }
    }
}

// ---------------- launch ----------------
extern "C" void kernel_launch(void* const* d_in, const int* in_sizes, int n_in,
                              void* d_out, int out_size) {
    (void)in_sizes; (void)n_in; (void)out_size;
    const float* t          = (const float*)d_in[0];
    const float* W_ih       = (const float*)d_in[1];
    const float* W_hh       = (const float*)d_in[2];
    const float* b_ih       = (const float*)d_in[3];
    const float* b_hh       = (const float*)d_in[4];
    const float* in_proj_w  = (const float*)d_in[5];
    const float* in_proj_b  = (const float*)d_in[6];
    const float* out_proj_w = (const float*)d_in[7];
    const float* out_proj_b = (const float*)d_in[8];
    const float* ln_w       = (const float*)d_in[9];
    const float* ln_b       = (const float*)d_in[10];
    const float* out_w      = (const float*)d_in[11];
    const float* out_b      = (const float*)d_in[12];
    float* out = (float*)d_out;

    lstm_kernel<<<NCHUNK, 128>>>(t, W_ih, W_hh, b_ih, b_hh, in_proj_w, in_proj_b);
    dim3 agrid(GAGG, NHEAD);
    agg_kernel<<<agrid, 512>>>();
    tqfin_kernel<<<GFIN, 256>>>(out_proj_w, out_proj_b, ln_w, ln_b,
                                out_w, out_b, out);
}